// round 2
// baseline (speedup 1.0000x reference)
#include <cuda_runtime.h>

#define T_STEPS 256
#define HCC 64
#define G4 256      // 4*HC
#define PP 55
#define BB 32

// ---------------- scratch (no allocation allowed) ----------------
__device__ float g_feat[2 * BB * 2 * HCC * PP];       // [sub][b][7040] rows=64, K=7040
__device__ float g_y1[64 * 3400];
__device__ float g_y2[64 * 1000];
__device__ float g_y3[64 * 512];
__device__ float g_part[8 * 64 * 3400];               // max KS*64*N

__device__ __forceinline__ float sigm_(float x) {
    return 1.0f / (1.0f + __expf(-x));
}
__device__ __forceinline__ float tanh_(float x) {
    return 2.0f / (1.0f + __expf(-2.0f * x)) - 1.0f;
}

// ---------------- recurrent kernel ----------------
// block = one (sub, cell, b, p) row; thread n owns gate column n (n in [0,256))
__global__ __launch_bounds__(256, 2)
void lstm_kernel(const float* __restrict__ x1, const float* __restrict__ x2,
                 const float* __restrict__ wx1, const float* __restrict__ wh1,
                 const float* __restrict__ bx1, const float* __restrict__ bh1,
                 const float* __restrict__ wx2, const float* __restrict__ wh2,
                 const float* __restrict__ bx2, const float* __restrict__ bh2,
                 float* __restrict__ feat)
{
    int bid = blockIdx.x;
    int p    = bid % PP;
    int b    = (bid / PP) % BB;
    int cell = (bid / (PP * BB)) & 1;
    int sub  = bid / (PP * BB * 2);

    const float* x  = sub  ? x2  : x1;
    const float* wx = cell ? wx2 : wx1;
    const float* wh = cell ? wh2 : wh1;
    const float* bx = cell ? bx2 : bx1;
    const float* bh = cell ? bh2 : bh1;

    int n = threadIdx.x;

    __shared__ float4 hsm4[16];          // h state, 64 floats
    __shared__ float  xrow[T_STEPS * 2]; // x[t][c] for this (b,p)
    __shared__ float  garr[256];
    __shared__ float  act[256];

    // wh column n into registers
    float w[64];
#pragma unroll
    for (int k = 0; k < 64; k++) w[k] = wh[k * G4 + n];
    float wxa  = wx[n];
    float wxb  = wx[G4 + n];
    float bsum = bx[n] + bh[n];

    // prefetch x row: x[((b*T+t)*IC+c)*P + p]
    {
        const float* xb = x + (size_t)b * T_STEPS * 2 * PP + p;
        for (int i = n; i < T_STEPS * 2; i += 256) {
            xrow[i] = xb[(size_t)i * PP];   // i = t*2+c
        }
    }
    if (n < 16) hsm4[n] = make_float4(0.f, 0.f, 0.f, 0.f);
    float cstate = 0.0f;                  // used by threads 0..63
    __syncthreads();

    float* hs = (float*)hsm4;

    for (int t = 0; t < T_STEPS; t++) {
        int tx = cell ? (T_STEPS - 1 - t) : t;
        float g  = bsum + xrow[2 * tx] * wxa + xrow[2 * tx + 1] * wxb;
        float g2 = 0.f;
#pragma unroll
        for (int j = 0; j < 16; j++) {
            float4 hv = hsm4[j];
            g  += hv.x * w[4 * j + 0];
            g2 += hv.y * w[4 * j + 1];
            g  += hv.z * w[4 * j + 2];
            g2 += hv.w * w[4 * j + 3];
        }
        garr[n] = g + g2;
        __syncthreads();

        {
            float v = garr[n];
            act[n] = (n < 192) ? sigm_(v) : tanh_(v);
        }
        __syncthreads();

        if (n < 64) {
            cstate = act[64 + n] * cstate + act[n] * act[192 + n];
            hs[n]  = act[128 + n] * tanh_(cstate);
        }
        __syncthreads();
    }

    // channel-major concat layout: feat[sub][b][cell*HC*P + c*P + p]
    if (n < 64) {
        feat[((size_t)sub * BB + b) * (2 * HCC * PP) + cell * HCC * PP + n * PP + p] = hs[n];
    }
}

// ---------------- FC: K-split GEMM partials + reduce ----------------
// X: (64, K) row-major; W: (K, N); writes Ppart[ks][64][N]
__global__ __launch_bounds__(256)
void gemm_part(const float* __restrict__ X, const float* __restrict__ W,
               float* __restrict__ Ppart, int N, int K, int KS)
{
    int n0 = blockIdx.x * 64;
    int ks = blockIdx.y;
    int k0s = (int)(((long)K * ks) / KS);
    int k1s = (int)(((long)K * (ks + 1)) / KS);

    __shared__ float Asm[64][17];
    __shared__ float Bsm[16][65];

    int tid = threadIdx.x;
    int nl  = tid & 63;
    int mg  = tid >> 6;   // 0..3

    float acc[16];
#pragma unroll
    for (int i = 0; i < 16; i++) acc[i] = 0.f;

    for (int k0 = k0s; k0 < k1s; k0 += 16) {
#pragma unroll
        for (int i = 0; i < 4; i++) {
            int r = (tid >> 4) + i * 16;
            int c = tid & 15;
            int k = k0 + c;
            Asm[r][c] = (k < k1s) ? X[(size_t)r * K + k] : 0.f;
        }
#pragma unroll
        for (int i = 0; i < 4; i++) {
            int r  = (tid >> 6) + i * 4;
            int c  = tid & 63;
            int k  = k0 + r;
            int nn = n0 + c;
            Bsm[r][c] = (k < k1s && nn < N) ? W[(size_t)k * N + nn] : 0.f;
        }
        __syncthreads();
#pragma unroll
        for (int kk = 0; kk < 16; kk++) {
            float bv = Bsm[kk][nl];
#pragma unroll
            for (int i = 0; i < 16; i++)
                acc[i] += Asm[mg * 16 + i][kk] * bv;
        }
        __syncthreads();
    }

    int nn = n0 + nl;
    if (nn < N) {
        float* outp = Ppart + (size_t)ks * 64 * N;
#pragma unroll
        for (int i = 0; i < 16; i++)
            outp[(size_t)(mg * 16 + i) * N + nn] = acc[i];
    }
}

__global__ void reduce_bias(const float* __restrict__ Ppart, const float* __restrict__ bias,
                            float* __restrict__ Y, int N, int KS)
{
    int idx = blockIdx.x * 256 + threadIdx.x;
    if (idx >= 64 * N) return;
    int nn = idx % N;
    float s = bias[nn];
    for (int ks = 0; ks < KS; ks++) s += Ppart[(size_t)ks * 64 * N + idx];
    Y[idx] = s;
}

// ---------------- launch ----------------
extern "C" void kernel_launch(void* const* d_in, const int* in_sizes, int n_in,
                              void* d_out, int out_size)
{
    const float* x1  = (const float*)d_in[0];
    const float* x2  = (const float*)d_in[1];
    const float* wx1 = (const float*)d_in[2];
    const float* wh1 = (const float*)d_in[3];
    const float* bx1 = (const float*)d_in[4];
    const float* bh1 = (const float*)d_in[5];
    const float* wx2 = (const float*)d_in[6];
    const float* wh2 = (const float*)d_in[7];
    const float* bx2 = (const float*)d_in[8];
    const float* bh2 = (const float*)d_in[9];
    const float* fw2 = (const float*)d_in[10];
    const float* fb2 = (const float*)d_in[11];
    const float* fw3 = (const float*)d_in[12];
    const float* fb3 = (const float*)d_in[13];
    const float* fw4 = (const float*)d_in[14];
    const float* fb4 = (const float*)d_in[15];
    const float* fw5 = (const float*)d_in[16];
    const float* fb5 = (const float*)d_in[17];

    float *feat, *y1, *y2, *y3, *part;
    cudaGetSymbolAddress((void**)&feat, g_feat);
    cudaGetSymbolAddress((void**)&y1,   g_y1);
    cudaGetSymbolAddress((void**)&y2,   g_y2);
    cudaGetSymbolAddress((void**)&y3,   g_y3);
    cudaGetSymbolAddress((void**)&part, g_part);

    // recurrent scan: 7040 independent rows
    lstm_kernel<<<2 * 2 * BB * PP, 256>>>(x1, x2, wx1, wh1, bx1, bh1,
                                          wx2, wh2, bx2, bh2, feat);

    // FC1: 7040 -> 3400
    gemm_part<<<dim3(54, 8), 256>>>(feat, fw2, part, 3400, 7040, 8);
    reduce_bias<<<(64 * 3400 + 255) / 256, 256>>>(part, fb2, y1, 3400, 8);
    // FC2: 3400 -> 1000
    gemm_part<<<dim3(16, 8), 256>>>(y1, fw3, part, 1000, 3400, 8);
    reduce_bias<<<(64 * 1000 + 255) / 256, 256>>>(part, fb3, y2, 1000, 8);
    // FC3: 1000 -> 500
    gemm_part<<<dim3(8, 4), 256>>>(y2, fw4, part, 500, 1000, 4);
    reduce_bias<<<(64 * 500 + 255) / 256, 256>>>(part, fb4, y3, 500, 4);
    // FC4: 500 -> 50 -> d_out (out1 rows 0..31, out2 rows 32..63)
    gemm_part<<<dim3(1, 2), 256>>>(y3, fw5, part, 50, 500, 2);
    reduce_bias<<<(64 * 50 + 255) / 256, 256>>>(part, fb5, (float*)d_out, 50, 2);
}

// round 3
// speedup vs baseline: 1.1681x; 1.1681x over previous
#include <cuda_runtime.h>

#define T_STEPS 256
#define HCC 64
#define G4 256      // 4*HC
#define PP 55
#define BB 32

// ---------------- scratch (no allocation allowed) ----------------
__device__ float g_feat[2 * BB * 2 * HCC * PP];       // [sub][b][7040] rows=64, K=7040
__device__ float g_y1[64 * 3400];
__device__ float g_y2[64 * 1000];
__device__ float g_y3[64 * 512];
__device__ float g_part[8 * 64 * 3400];               // max KS*64*N

__device__ __forceinline__ float sigm_(float x) {
    return 1.0f / (1.0f + __expf(-x));
}
__device__ __forceinline__ float tanh_(float x) {
    return 2.0f / (1.0f + __expf(-2.0f * x)) - 1.0f;
}

// ---------------- packed f32x2 helpers ----------------
__device__ __forceinline__ unsigned long long pack2(float lo, float hi) {
    unsigned long long r;
    asm("mov.b64 %0, {%1, %2};" : "=l"(r) : "f"(lo), "f"(hi));
    return r;
}
__device__ __forceinline__ void unpack2(unsigned long long v, float& lo, float& hi) {
    asm("mov.b64 {%0, %1}, %2;" : "=f"(lo), "=f"(hi) : "l"(v));
}
__device__ __forceinline__ void ffma2(unsigned long long& d,
                                      unsigned long long a, unsigned long long b) {
    asm("fma.rn.f32x2 %0, %1, %2, %0;" : "+l"(d) : "l"(a), "l"(b));
}
__device__ __forceinline__ unsigned long long fadd2(unsigned long long a, unsigned long long b) {
    unsigned long long r;
    asm("add.rn.f32x2 %0, %1, %2;" : "=l"(r) : "l"(a), "l"(b));
    return r;
}

// ---------------- recurrent kernel ----------------
// block = one (sub, cell, b, p) row; 128 threads; thread n owns gate columns n and n+128.
// Column layout: gates i,f,o,g at [0,64),[64,128),[128,192),[192,256).
//   n in [0,64):   cols n   (i, sigmoid)  and n+128 (o, sigmoid)
//   n in [64,128): cols n   (f, sigmoid)  and n+128 (g, tanh)
__global__ __launch_bounds__(128, 3)
void lstm_kernel(const float* __restrict__ x1, const float* __restrict__ x2,
                 const float* __restrict__ wx1, const float* __restrict__ wh1,
                 const float* __restrict__ bx1, const float* __restrict__ bh1,
                 const float* __restrict__ wx2, const float* __restrict__ wh2,
                 const float* __restrict__ bx2, const float* __restrict__ bh2,
                 float* __restrict__ feat)
{
    int bid = blockIdx.x;
    int p    = bid % PP;
    int b    = (bid / PP) % BB;
    int cell = (bid / (PP * BB)) & 1;
    int sub  = bid / (PP * BB * 2);

    const float* x  = sub  ? x2  : x1;
    const float* wx = cell ? wx2 : wx1;
    const float* wh = cell ? wh2 : wh1;
    const float* bx = cell ? bx2 : bx1;
    const float* bh = cell ? bh2 : bh1;

    int n = threadIdx.x;   // 0..127

    __shared__ float2 hdup[64];           // h[k] duplicated in both halves
    __shared__ float  xrow[T_STEPS * 2];  // x[t][c] for this (b,p)
    __shared__ float  act[256];           // activations by gate column

    // packed column-pair weights into registers: wpk[k] = (wh[k][n], wh[k][n+128])
    unsigned long long wpk[64];
#pragma unroll
    for (int k = 0; k < 64; k++)
        wpk[k] = pack2(wh[k * G4 + n], wh[k * G4 + n + 128]);
    unsigned long long wxa2 = pack2(wx[n],      wx[n + 128]);
    unsigned long long wxb2 = pack2(wx[G4 + n], wx[G4 + n + 128]);
    unsigned long long b2   = pack2(bx[n] + bh[n], bx[n + 128] + bh[n + 128]);

    // prefetch x row: x[((b*T+t)*IC+c)*P + p], i = t*2+c
    {
        const float* xb = x + (size_t)b * T_STEPS * 2 * PP + p;
        for (int i = n; i < T_STEPS * 2; i += 128)
            xrow[i] = xb[(size_t)i * PP];
    }
    if (n < 64) hdup[n] = make_float2(0.f, 0.f);
    float cst = 0.0f;                     // c-state, threads 0..63
    __syncthreads();

    const unsigned long long* hq = (const unsigned long long*)hdup;

    for (int t = 0; t < T_STEPS; t++) {
        int tx = cell ? (T_STEPS - 1 - t) : t;
        float xa = xrow[2 * tx];
        float xv = xrow[2 * tx + 1];

        unsigned long long acc0 = b2;
        unsigned long long acc1 = 0ull;
        ffma2(acc0, pack2(xa, xa), wxa2);
        ffma2(acc1, pack2(xv, xv), wxb2);
#pragma unroll
        for (int k = 0; k < 64; k += 2) {
            ffma2(acc0, hq[k],     wpk[k]);
            ffma2(acc1, hq[k + 1], wpk[k + 1]);
        }
        float glo, ghi;
        unpack2(fadd2(acc0, acc1), glo, ghi);

        act[n]       = sigm_(glo);                       // i (n<64) or f (n>=64)
        act[n + 128] = (n < 64) ? sigm_(ghi) : tanh_(ghi); // o or g
        __syncthreads();

        if (n < 64) {
            cst = act[64 + n] * cst + act[n] * act[192 + n];
            float h = act[128 + n] * tanh_(cst);
            hdup[n] = make_float2(h, h);
        }
        __syncthreads();
    }

    // channel-major concat layout: feat[sub][b][cell*HC*P + c*P + p]
    if (n < 64) {
        feat[((size_t)sub * BB + b) * (2 * HCC * PP) + cell * HCC * PP + n * PP + p]
            = hdup[n].x;
    }
}

// ---------------- FC: K-split GEMM partials + reduce ----------------
// X: (64, K) row-major; W: (K, N); writes Ppart[ks][64][N]
__global__ __launch_bounds__(256)
void gemm_part(const float* __restrict__ X, const float* __restrict__ W,
               float* __restrict__ Ppart, int N, int K, int KS)
{
    int n0 = blockIdx.x * 64;
    int ks = blockIdx.y;
    int k0s = (int)(((long)K * ks) / KS);
    int k1s = (int)(((long)K * (ks + 1)) / KS);

    __shared__ float Asm[64][17];
    __shared__ float Bsm[16][65];

    int tid = threadIdx.x;
    int nl  = tid & 63;
    int mg  = tid >> 6;   // 0..3

    float acc[16];
#pragma unroll
    for (int i = 0; i < 16; i++) acc[i] = 0.f;

    for (int k0 = k0s; k0 < k1s; k0 += 16) {
#pragma unroll
        for (int i = 0; i < 4; i++) {
            int r = (tid >> 4) + i * 16;
            int c = tid & 15;
            int k = k0 + c;
            Asm[r][c] = (k < k1s) ? X[(size_t)r * K + k] : 0.f;
        }
#pragma unroll
        for (int i = 0; i < 4; i++) {
            int r  = (tid >> 6) + i * 4;
            int c  = tid & 63;
            int k  = k0 + r;
            int nn = n0 + c;
            Bsm[r][c] = (k < k1s && nn < N) ? W[(size_t)k * N + nn] : 0.f;
        }
        __syncthreads();
#pragma unroll
        for (int kk = 0; kk < 16; kk++) {
            float bv = Bsm[kk][nl];
#pragma unroll
            for (int i = 0; i < 16; i++)
                acc[i] += Asm[mg * 16 + i][kk] * bv;
        }
        __syncthreads();
    }

    int nn = n0 + nl;
    if (nn < N) {
        float* outp = Ppart + (size_t)ks * 64 * N;
#pragma unroll
        for (int i = 0; i < 16; i++)
            outp[(size_t)(mg * 16 + i) * N + nn] = acc[i];
    }
}

__global__ void reduce_bias(const float* __restrict__ Ppart, const float* __restrict__ bias,
                            float* __restrict__ Y, int N, int KS)
{
    int idx = blockIdx.x * 256 + threadIdx.x;
    if (idx >= 64 * N) return;
    int nn = idx % N;
    float s = bias[nn];
    for (int ks = 0; ks < KS; ks++) s += Ppart[(size_t)ks * 64 * N + idx];
    Y[idx] = s;
}

// ---------------- launch ----------------
extern "C" void kernel_launch(void* const* d_in, const int* in_sizes, int n_in,
                              void* d_out, int out_size)
{
    const float* x1  = (const float*)d_in[0];
    const float* x2  = (const float*)d_in[1];
    const float* wx1 = (const float*)d_in[2];
    const float* wh1 = (const float*)d_in[3];
    const float* bx1 = (const float*)d_in[4];
    const float* bh1 = (const float*)d_in[5];
    const float* wx2 = (const float*)d_in[6];
    const float* wh2 = (const float*)d_in[7];
    const float* bx2 = (const float*)d_in[8];
    const float* bh2 = (const float*)d_in[9];
    const float* fw2 = (const float*)d_in[10];
    const float* fb2 = (const float*)d_in[11];
    const float* fw3 = (const float*)d_in[12];
    const float* fb3 = (const float*)d_in[13];
    const float* fw4 = (const float*)d_in[14];
    const float* fb4 = (const float*)d_in[15];
    const float* fw5 = (const float*)d_in[16];
    const float* fb5 = (const float*)d_in[17];

    float *feat, *y1, *y2, *y3, *part;
    cudaGetSymbolAddress((void**)&feat, g_feat);
    cudaGetSymbolAddress((void**)&y1,   g_y1);
    cudaGetSymbolAddress((void**)&y2,   g_y2);
    cudaGetSymbolAddress((void**)&y3,   g_y3);
    cudaGetSymbolAddress((void**)&part, g_part);

    // recurrent scan: 7040 independent rows
    lstm_kernel<<<2 * 2 * BB * PP, 128>>>(x1, x2, wx1, wh1, bx1, bh1,
                                          wx2, wh2, bx2, bh2, feat);

    // FC1: 7040 -> 3400
    gemm_part<<<dim3(54, 8), 256>>>(feat, fw2, part, 3400, 7040, 8);
    reduce_bias<<<(64 * 3400 + 255) / 256, 256>>>(part, fb2, y1, 3400, 8);
    // FC2: 3400 -> 1000
    gemm_part<<<dim3(16, 8), 256>>>(y1, fw3, part, 1000, 3400, 8);
    reduce_bias<<<(64 * 1000 + 255) / 256, 256>>>(part, fb3, y2, 1000, 8);
    // FC3: 1000 -> 500
    gemm_part<<<dim3(8, 4), 256>>>(y2, fw4, part, 500, 1000, 4);
    reduce_bias<<<(64 * 500 + 255) / 256, 256>>>(part, fb4, y3, 500, 4);
    // FC4: 500 -> 50 -> d_out (out1 rows 0..31, out2 rows 32..63)
    gemm_part<<<dim3(1, 2), 256>>>(y3, fw5, part, 50, 500, 2);
    reduce_bias<<<(64 * 50 + 255) / 256, 256>>>(part, fb5, (float*)d_out, 50, 2);
}

// round 6
// speedup vs baseline: 4.7896x; 4.1003x over previous
#include <cuda_runtime.h>
#include <cuda_fp16.h>
#include <cstdint>

#define RS   88                 // halves per smem row (176 B, conflict-free pad)
#define ASZH (64 * RS)          // halves per A buffer (64 rows)
#define SMEM_BYTES ((2 * ASZH + 256 * RS) * 2)

// ---------------- scratch ----------------
__device__ float g_feat[2 * 32 * 2 * 64 * 55];   // [sub][b][7040]
__device__ float g_y1[64 * 3400];
__device__ float g_y2[64 * 1000];
__device__ float g_y3[64 * 512];
__device__ float g_part[8 * 64 * 3400];

__device__ __forceinline__ float tanh_f(float x) {
    float r; asm("tanh.approx.f32 %0, %1;" : "=f"(r) : "f"(x)); return r;
}
__device__ __forceinline__ float sigm_f(float x) { return fmaf(0.5f, tanh_f(0.5f * x), 0.5f); }

__device__ __forceinline__ uint32_t smem_u32(const void* p) {
    uint32_t a;
    asm("{ .reg .u64 t; cvta.to.shared.u64 t, %1; cvt.u32.u64 %0, t; }" : "=r"(a) : "l"(p));
    return a;
}

#define MMA16816(d, a0, a1, a2, a3, b0, b1) \
    asm volatile("mma.sync.aligned.m16n8k16.row.col.f32.f16.f16.f32 " \
        "{%0,%1,%2,%3}, {%4,%5,%6,%7}, {%8,%9}, {%0,%1,%2,%3};" \
        : "+f"((d)[0]), "+f"((d)[1]), "+f"((d)[2]), "+f"((d)[3]) \
        : "r"(a0), "r"(a1), "r"(a2), "r"(a3), "r"(b0), "r"(b1))

// ---------------- tensor-core LSTM (portable HMMA) ----------------
// 110 blocks; block = 64 rows of one cell. 8 warps; warp w owns channels [8w, 8w+8).
// B col n = 32*warp + 8*gate + ch_in_group  ->  weight col gate*64 + 8*warp + ch_in_group.
__global__ __launch_bounds__(256, 1)
void lstm_mma(const float* __restrict__ x1, const float* __restrict__ x2,
              const float* __restrict__ wx1, const float* __restrict__ wh1,
              const float* __restrict__ bx1, const float* __restrict__ bh1,
              const float* __restrict__ wx2, const float* __restrict__ wh2,
              const float* __restrict__ bx2, const float* __restrict__ bh2,
              float* __restrict__ feat)
{
    extern __shared__ __align__(16) __half smem[];
    __half* A0 = smem;
    __half* A1 = smem + ASZH;
    __half* Bw = smem + 2 * ASZH;

    int tid = threadIdx.x, wid = tid >> 5, lane = tid & 31;
    int blk = blockIdx.x;
    int cell = blk / 55;

    const float* wh = cell ? wh2 : wh1;
    const float* wx = cell ? wx2 : wx1;
    const float* bx = cell ? bx2 : bx1;
    const float* bh = cell ? bh2 : bh1;

    // ---- build B (weights, fp16) ----
    {
        int n  = tid;
        int w  = n >> 5, g = (n >> 3) & 3, cl = n & 7;
        int gc = g * 64 + 8 * w + cl;                 // source gate column
        __half* bp = Bw + n * RS;
#pragma unroll 8
        for (int k = 0; k < 64; k++) bp[k] = __float2half(wh[k * 256 + gc]);
        bp[64] = __float2half(wx[gc]);
        bp[65] = __float2half(wx[256 + gc]);
        bp[66] = __float2half(bx[gc] + bh[gc]);
#pragma unroll
        for (int k = 67; k < RS; k++) bp[k] = __float2half(0.f);
    }
    // ---- zero A buffers ----
    for (int i = tid; i < (2 * ASZH * 2) / 16; i += 256)
        ((uint4*)smem)[i] = make_uint4(0, 0, 0, 0);
    __syncthreads();

    // per-row x pointer (threads 0..63 own row tid)
    const float* xrp = nullptr;
    if (tid < 64) {
        int ric = (blk % 55) * 64 + tid;
        int sub = ric / 1760, rem = ric % 1760, b = rem / 55, p = rem % 55;
        xrp = (sub ? x2 : x1) + (size_t)b * 256 * 110 + p;
        int t0 = cell ? 255 : 0;
        A0[tid * RS + 64] = __float2half(xrp[t0 * 110]);
        A0[tid * RS + 65] = __float2half(xrp[t0 * 110 + 55]);
        A0[tid * RS + 66] = __float2half(1.f);
        A1[tid * RS + 66] = __float2half(1.f);
    }
    __syncthreads();

    // ---- load static B fragments into registers ----
    uint32_t bf[4][5][2];
    {
        int li = lane & 15;
#pragma unroll
        for (int nt = 0; nt < 4; nt++)
#pragma unroll
            for (int kt = 0; kt < 5; kt++) {
                uint32_t addr = smem_u32(Bw + (wid * 32 + nt * 8 + (li & 7)) * RS
                                            + kt * 16 + ((li >> 3) & 1) * 8);
                asm volatile("ldmatrix.sync.aligned.m8n8.x2.shared.b16 {%0,%1}, [%2];"
                             : "=r"(bf[nt][kt][0]), "=r"(bf[nt][kt][1]) : "r"(addr));
            }
    }

    // per-lane A-ldmatrix offset (bytes): row-part + k-half select
    uint32_t laneoff = (uint32_t)(((lane & 7) + 8 * ((lane >> 3) & 1)) * RS * 2
                                  + (lane >> 4) * 16);

    float cst[4][4];
#pragma unroll
    for (int mt = 0; mt < 4; mt++)
#pragma unroll
        for (int j = 0; j < 4; j++) cst[mt][j] = 0.f;

    int rowa_base = lane >> 2;
    int ch = wid * 8 + (lane & 3) * 2;

    float xn0 = 0.f, xn1 = 0.f;

    for (int t = 0; t < 256; t++) {
        __half* Ac = (t & 1) ? A1 : A0;
        __half* An = (t & 1) ? A0 : A1;
        uint32_t abase = smem_u32(Ac) + laneoff;

        // prefetch x(t+1) (hidden under MMA latency)
        if (tid < 64 && t < 255) {
            int tx = cell ? 254 - t : t + 1;
            xn0 = xrp[(size_t)tx * 110];
            xn1 = xrp[(size_t)tx * 110 + 55];
        }

        float acc[4][4][4];
#pragma unroll
        for (int mt = 0; mt < 4; mt++)
#pragma unroll
            for (int nt = 0; nt < 4; nt++)
#pragma unroll
                for (int j = 0; j < 4; j++) acc[mt][nt][j] = 0.f;

#pragma unroll
        for (int mt = 0; mt < 4; mt++) {
#pragma unroll
            for (int kt = 0; kt < 5; kt++) {
                uint32_t a0, a1, a2, a3;
                uint32_t addr = abase + (uint32_t)((mt * 16 * RS + kt * 16) * 2);
                asm volatile("ldmatrix.sync.aligned.m8n8.x4.shared.b16 {%0,%1,%2,%3}, [%4];"
                             : "=r"(a0), "=r"(a1), "=r"(a2), "=r"(a3) : "r"(addr));
                MMA16816(acc[mt][0], a0, a1, a2, a3, bf[0][kt][0], bf[0][kt][1]);
                MMA16816(acc[mt][1], a0, a1, a2, a3, bf[1][kt][0], bf[1][kt][1]);
                MMA16816(acc[mt][2], a0, a1, a2, a3, bf[2][kt][0], bf[2][kt][1]);
                MMA16816(acc[mt][3], a0, a1, a2, a3, bf[3][kt][0], bf[3][kt][1]);
            }
        }

        // epilogue: nt = gate (0:i, 1:f, 2:o, 3:g); lane owns rows {a, a+8}, chans {ch, ch+1}
#pragma unroll
        for (int mt = 0; mt < 4; mt++) {
            float hv[4];
#pragma unroll
            for (int j = 0; j < 4; j++) {
                float iv = sigm_f(acc[mt][0][j]);
                float fv = sigm_f(acc[mt][1][j]);
                float ov = sigm_f(acc[mt][2][j]);
                float gv = tanh_f(acc[mt][3][j]);
                float cn = fmaf(fv, cst[mt][j], iv * gv);
                cst[mt][j] = cn;
                hv[j] = ov * tanh_f(cn);
            }
            int rowa = mt * 16 + rowa_base;
            *(__half2*)(An + rowa * RS + ch)       = __floats2half2_rn(hv[0], hv[1]);
            *(__half2*)(An + (rowa + 8) * RS + ch) = __floats2half2_rn(hv[2], hv[3]);

            if (t == 255) {
#pragma unroll
                for (int j = 0; j < 4; j++) {
                    int row = rowa + ((j >> 1) ? 8 : 0);
                    int chh = ch + (j & 1);
                    int ric = (blk % 55) * 64 + row;
                    int sub = ric / 1760, rem = ric % 1760, bb = rem / 55, pp = rem % 55;
                    feat[(size_t)(sub * 32 + bb) * 7040 + cell * 3520 + chh * 55 + pp] = hv[j];
                }
            }
        }

        if (tid < 64 && t < 255)
            *(__half2*)(An + tid * RS + 64) = __floats2half2_rn(xn0, xn1);

        __syncthreads();
    }
}

// ---------------- FC: K-split GEMM partials + reduce ----------------
__global__ __launch_bounds__(256)
void gemm_part(const float* __restrict__ X, const float* __restrict__ W,
               float* __restrict__ Ppart, int N, int K, int KS)
{
    int n0 = blockIdx.x * 64;
    int ks = blockIdx.y;
    int k0s = (int)(((long)K * ks) / KS);
    int k1s = (int)(((long)K * (ks + 1)) / KS);

    __shared__ float Asm[64][17];
    __shared__ float Bsm[16][65];

    int tid = threadIdx.x;
    int nl  = tid & 63;
    int mg  = tid >> 6;

    float acc[16];
#pragma unroll
    for (int i = 0; i < 16; i++) acc[i] = 0.f;

    for (int k0 = k0s; k0 < k1s; k0 += 16) {
#pragma unroll
        for (int i = 0; i < 4; i++) {
            int rr = (tid >> 4) + i * 16;
            int cc = tid & 15;
            int k = k0 + cc;
            Asm[rr][cc] = (k < k1s) ? X[(size_t)rr * K + k] : 0.f;
        }
#pragma unroll
        for (int i = 0; i < 4; i++) {
            int rr = (tid >> 6) + i * 4;
            int cc = tid & 63;
            int k  = k0 + rr;
            int nn = n0 + cc;
            Bsm[rr][cc] = (k < k1s && nn < N) ? W[(size_t)k * N + nn] : 0.f;
        }
        __syncthreads();
#pragma unroll
        for (int kk = 0; kk < 16; kk++) {
            float bv = Bsm[kk][nl];
#pragma unroll
            for (int i = 0; i < 16; i++)
                acc[i] += Asm[mg * 16 + i][kk] * bv;
        }
        __syncthreads();
    }

    int nn = n0 + nl;
    if (nn < N) {
        float* outp = Ppart + (size_t)ks * 64 * N;
#pragma unroll
        for (int i = 0; i < 16; i++)
            outp[(size_t)(mg * 16 + i) * N + nn] = acc[i];
    }
}

__global__ void reduce_bias(const float* __restrict__ Ppart, const float* __restrict__ bias,
                            float* __restrict__ Y, int N, int KS)
{
    int idx = blockIdx.x * 256 + threadIdx.x;
    if (idx >= 64 * N) return;
    int nn = idx % N;
    float s = bias[nn];
    for (int ks = 0; ks < KS; ks++) s += Ppart[(size_t)ks * 64 * N + idx];
    Y[idx] = s;
}

// ---------------- launch ----------------
extern "C" void kernel_launch(void* const* d_in, const int* in_sizes, int n_in,
                              void* d_out, int out_size)
{
    const float* x1  = (const float*)d_in[0];
    const float* x2  = (const float*)d_in[1];
    const float* wx1 = (const float*)d_in[2];
    const float* wh1 = (const float*)d_in[3];
    const float* bx1 = (const float*)d_in[4];
    const float* bh1 = (const float*)d_in[5];
    const float* wx2 = (const float*)d_in[6];
    const float* wh2 = (const float*)d_in[7];
    const float* bx2 = (const float*)d_in[8];
    const float* bh2 = (const float*)d_in[9];
    const float* fw2 = (const float*)d_in[10];
    const float* fb2 = (const float*)d_in[11];
    const float* fw3 = (const float*)d_in[12];
    const float* fb3 = (const float*)d_in[13];
    const float* fw4 = (const float*)d_in[14];
    const float* fb4 = (const float*)d_in[15];
    const float* fw5 = (const float*)d_in[16];
    const float* fb5 = (const float*)d_in[17];

    float *feat, *y1, *y2, *y3, *part;
    cudaGetSymbolAddress((void**)&feat, g_feat);
    cudaGetSymbolAddress((void**)&y1,   g_y1);
    cudaGetSymbolAddress((void**)&y2,   g_y2);
    cudaGetSymbolAddress((void**)&y3,   g_y3);
    cudaGetSymbolAddress((void**)&part, g_part);

    cudaFuncSetAttribute(lstm_mma, cudaFuncAttributeMaxDynamicSharedMemorySize, SMEM_BYTES);

    lstm_mma<<<110, 256, SMEM_BYTES>>>(x1, x2, wx1, wh1, bx1, bh1,
                                       wx2, wh2, bx2, bh2, feat);

    // FC1: 7040 -> 3400
    gemm_part<<<dim3(54, 8), 256>>>(feat, fw2, part, 3400, 7040, 8);
    reduce_bias<<<(64 * 3400 + 255) / 256, 256>>>(part, fb2, y1, 3400, 8);
    // FC2: 3400 -> 1000
    gemm_part<<<dim3(16, 8), 256>>>(y1, fw3, part, 1000, 3400, 8);
    reduce_bias<<<(64 * 1000 + 255) / 256, 256>>>(part, fb3, y2, 1000, 8);
    // FC3: 1000 -> 500
    gemm_part<<<dim3(8, 4), 256>>>(y2, fw4, part, 500, 1000, 4);
    reduce_bias<<<(64 * 500 + 255) / 256, 256>>>(part, fb4, y3, 500, 4);
    // FC4: 500 -> 50 -> d_out
    gemm_part<<<dim3(1, 2), 256>>>(y3, fw5, part, 50, 500, 2);
    reduce_bias<<<(64 * 50 + 255) / 256, 256>>>(part, fb5, (float*)d_out, 50, 2);
}

// round 8
// speedup vs baseline: 5.6794x; 1.1858x over previous
#include <cuda_runtime.h>
#include <cuda_fp16.h>
#include <cstdint>

#define RS   88                 // halves per smem row (176 B)
#define MB   48                 // rows per block
#define ASZH (MB * RS)          // halves per A buffer
#define SMEM_BYTES ((2 * ASZH + 256 * RS) * 2)

// ---------------- scratch ----------------
__device__ float g_feat[2 * 32 * 2 * 64 * 55];   // [sub][b][7040]
__device__ float g_y1[64 * 3400];
__device__ float g_y2[64 * 1000];
__device__ float g_y3[64 * 512];
__device__ float g_part[16 * 64 * 3400];

__device__ __forceinline__ float tanh_f(float x) {
    float r; asm("tanh.approx.f32 %0, %1;" : "=f"(r) : "f"(x)); return r;
}
// pre-activation already scaled by 0.5 (folded into weights)
__device__ __forceinline__ float sigm_pre(float xhalf) {
    return fmaf(0.5f, tanh_f(xhalf), 0.5f);
}

__device__ __forceinline__ uint32_t smem_u32(const void* p) {
    uint32_t a;
    asm("{ .reg .u64 t; cvta.to.shared.u64 t, %1; cvt.u32.u64 %0, t; }" : "=r"(a) : "l"(p));
    return a;
}

#define MMA16816(d, a0, a1, a2, a3, b0, b1) \
    asm volatile("mma.sync.aligned.m16n8k16.row.col.f32.f16.f16.f32 " \
        "{%0,%1,%2,%3}, {%4,%5,%6,%7}, {%8,%9}, {%0,%1,%2,%3};" \
        : "+f"((d)[0]), "+f"((d)[1]), "+f"((d)[2]), "+f"((d)[3]) \
        : "r"(a0), "r"(a1), "r"(a2), "r"(a3), "r"(b0), "r"(b1))

// ---------------- tensor-core LSTM (portable HMMA, 16 warps) ----------------
// grid = 148: blk/74 = cell, rows (blk%74)*48 within cell-space (3520, padded to 3552).
// Warp w owns B cols [16w,16w+16): tile0 cols 2c+{0,1} = channel 4w+c gates (i,f),
// tile1 = gates (o,g). Lane quad c -> channel 4w+c; full gate quad in-lane.
__global__ __launch_bounds__(512, 1)
void lstm_mma(const float* __restrict__ x1, const float* __restrict__ x2,
              const float* __restrict__ wx1, const float* __restrict__ wh1,
              const float* __restrict__ bx1, const float* __restrict__ bh1,
              const float* __restrict__ wx2, const float* __restrict__ wh2,
              const float* __restrict__ bx2, const float* __restrict__ bh2,
              float* __restrict__ feat)
{
    extern __shared__ __align__(16) __half smem[];
    __half* A0 = smem;
    __half* A1 = smem + ASZH;
    __half* Bw = smem + 2 * ASZH;

    int tid = threadIdx.x, wid = tid >> 5, lane = tid & 31;
    int blk = blockIdx.x;
    int cell = blk / 74;
    int rb   = (blk % 74) * MB;              // row base within cell-space

    const float* wh = cell ? wh2 : wh1;
    const float* wx = cell ? wx2 : wx1;
    const float* bx = cell ? bx2 : bx1;
    const float* bh = cell ? bh2 : bh1;

    // ---- build B (fp16, 0.5-prescaled for sigmoid gates) ----
    if (tid < 256) {
        int n  = tid;
        int w  = n >> 4, hi = (n >> 3) & 1, c = (n >> 1) & 3;
        int gg = (n & 1) + 2 * hi;           // 0:i 1:f 2:o 3:g
        int gc = gg * 64 + 4 * w + c;        // source gate column
        float s = (gg == 3) ? 1.0f : 0.5f;
        __half* bp = Bw + n * RS;
#pragma unroll 8
        for (int k = 0; k < 64; k++) bp[k] = __float2half(wh[k * 256 + gc] * s);
        bp[64] = __float2half(wx[gc] * s);
        bp[65] = __float2half(wx[256 + gc] * s);
        bp[66] = __float2half((bx[gc] + bh[gc]) * s);
#pragma unroll
        for (int k = 67; k < RS; k++) bp[k] = __float2half(0.f);
    }
    // ---- zero A buffers ----
    for (int i = tid; i < (2 * ASZH * 2) / 16; i += 512)
        ((uint4*)smem)[i] = make_uint4(0, 0, 0, 0);
    __syncthreads();

    // per-row x pointer (threads 0..47 own row tid)
    const float* xrp = nullptr;
    bool xvalid = false;
    if (tid < MB) {
        int ric = rb + tid;
        xvalid = ric < 3520;
        int ricc = xvalid ? ric : 0;
        int sub = ricc / 1760, rem = ricc % 1760, b = rem / 55, p = rem % 55;
        xrp = (sub ? x2 : x1) + (size_t)b * 256 * 110 + p;
        int t0 = cell ? 255 : 0;
        float xa = xvalid ? xrp[(size_t)t0 * 110]      : 0.f;
        float xc = xvalid ? xrp[(size_t)t0 * 110 + 55] : 0.f;
        A0[tid * RS + 64] = __float2half(xa);
        A0[tid * RS + 65] = __float2half(xc);
        A0[tid * RS + 66] = __float2half(1.f);
        A1[tid * RS + 66] = __float2half(1.f);
    }
    __syncthreads();

    // ---- static B fragments ----
    uint32_t bf[2][5][2];
    {
        int li = lane & 15;
#pragma unroll
        for (int nt = 0; nt < 2; nt++)
#pragma unroll
            for (int kt = 0; kt < 5; kt++) {
                uint32_t addr = smem_u32(Bw + (wid * 16 + nt * 8 + (li & 7)) * RS
                                            + kt * 16 + ((li >> 3) & 1) * 8);
                asm volatile("ldmatrix.sync.aligned.m8n8.x2.shared.b16 {%0,%1}, [%2];"
                             : "=r"(bf[nt][kt][0]), "=r"(bf[nt][kt][1]) : "r"(addr));
            }
    }

    uint32_t laneoff = (uint32_t)(((lane & 7) + 8 * ((lane >> 3) & 1)) * RS * 2
                                  + (lane >> 4) * 16);

    float cst[3][2];
#pragma unroll
    for (int mt = 0; mt < 3; mt++) { cst[mt][0] = 0.f; cst[mt][1] = 0.f; }

    int rowa = lane >> 2;
    int ch   = wid * 4 + (lane & 3);

    float xn0 = 0.f, xn1 = 0.f;

    for (int t = 0; t < 256; t++) {
        __half* Ac = (t & 1) ? A1 : A0;
        __half* An = (t & 1) ? A0 : A1;
        uint32_t abase = smem_u32(Ac) + laneoff;

        if (tid < MB && t < 255) {
            int tx = cell ? 254 - t : t + 1;
            xn0 = xvalid ? xrp[(size_t)tx * 110]      : 0.f;
            xn1 = xvalid ? xrp[(size_t)tx * 110 + 55] : 0.f;
        }

        float acc[3][2][4];
#pragma unroll
        for (int mt = 0; mt < 3; mt++)
#pragma unroll
            for (int nt = 0; nt < 2; nt++)
#pragma unroll
                for (int j = 0; j < 4; j++) acc[mt][nt][j] = 0.f;

#pragma unroll
        for (int mt = 0; mt < 3; mt++) {
#pragma unroll
            for (int kt = 0; kt < 5; kt++) {
                uint32_t a0, a1, a2, a3;
                uint32_t addr = abase + (uint32_t)((mt * 16 * RS + kt * 16) * 2);
                asm volatile("ldmatrix.sync.aligned.m8n8.x4.shared.b16 {%0,%1,%2,%3}, [%4];"
                             : "=r"(a0), "=r"(a1), "=r"(a2), "=r"(a3) : "r"(addr));
                MMA16816(acc[mt][0], a0, a1, a2, a3, bf[0][kt][0], bf[0][kt][1]);
                MMA16816(acc[mt][1], a0, a1, a2, a3, bf[1][kt][0], bf[1][kt][1]);
            }
        }

        // epilogue: lane owns channel ch, rows {mt*16+rowa, +8}
#pragma unroll
        for (int mt = 0; mt < 3; mt++) {
            float iv0 = sigm_pre(acc[mt][0][0]);
            float fv0 = sigm_pre(acc[mt][0][1]);
            float ov0 = sigm_pre(acc[mt][1][0]);
            float gv0 = tanh_f(acc[mt][1][1]);
            float c0  = fmaf(fv0, cst[mt][0], iv0 * gv0);
            cst[mt][0] = c0;
            float h0  = ov0 * tanh_f(c0);

            float iv1 = sigm_pre(acc[mt][0][2]);
            float fv1 = sigm_pre(acc[mt][0][3]);
            float ov1 = sigm_pre(acc[mt][1][2]);
            float gv1 = tanh_f(acc[mt][1][3]);
            float c1  = fmaf(fv1, cst[mt][1], iv1 * gv1);
            cst[mt][1] = c1;
            float h1  = ov1 * tanh_f(c1);

            int r0 = mt * 16 + rowa;
            An[r0 * RS + ch]       = __float2half(h0);
            An[(r0 + 8) * RS + ch] = __float2half(h1);

            if (t == 255) {
                int ric0 = rb + r0;
                if (ric0 < 3520) {
                    int sub = ric0 / 1760, rem = ric0 % 1760, bb = rem / 55, pp = rem % 55;
                    feat[(size_t)(sub * 32 + bb) * 7040 + cell * 3520 + ch * 55 + pp] = h0;
                }
                int ric1 = ric0 + 8;
                if (ric1 < 3520) {
                    int sub = ric1 / 1760, rem = ric1 % 1760, bb = rem / 55, pp = rem % 55;
                    feat[(size_t)(sub * 32 + bb) * 7040 + cell * 3520 + ch * 55 + pp] = h1;
                }
            }
        }

        if (tid < MB && t < 255)
            *(__half2*)(An + tid * RS + 64) = __floats2half2_rn(xn0, xn1);

        __syncthreads();
    }
}

// ---------------- FC: K-split GEMM partials + reduce ----------------
__global__ __launch_bounds__(256)
void gemm_part(const float* __restrict__ X, const float* __restrict__ W,
               float* __restrict__ Ppart, int N, int K, int KS)
{
    int n0 = blockIdx.x * 64;
    int ks = blockIdx.y;
    int k0s = (int)(((long)K * ks) / KS);
    int k1s = (int)(((long)K * (ks + 1)) / KS);

    __shared__ float Asm[64][17];
    __shared__ float Bsm[16][65];

    int tid = threadIdx.x;
    int nl  = tid & 63;
    int mg  = tid >> 6;

    bool vec_ok = ((N & 3) == 0);   // float4 path only when W rows stay 16B-aligned

    float acc[16];
#pragma unroll
    for (int i = 0; i < 16; i++) acc[i] = 0.f;

    for (int k0 = k0s; k0 < k1s; k0 += 16) {
#pragma unroll
        for (int i = 0; i < 4; i++) {
            int rr = (tid >> 4) + i * 16;
            int cc = tid & 15;
            int k = k0 + cc;
            Asm[rr][cc] = (k < k1s) ? X[(size_t)rr * K + k] : 0.f;
        }
        {
            int rr = tid >> 4;            // 0..15
            int c4 = (tid & 15) * 4;      // 0..60
            int k  = k0 + rr;
            int nn = n0 + c4;
            if (vec_ok && k < k1s && nn + 3 < N) {
                float4 v = *(const float4*)&W[(size_t)k * N + nn];
                Bsm[rr][c4]     = v.x;
                Bsm[rr][c4 + 1] = v.y;
                Bsm[rr][c4 + 2] = v.z;
                Bsm[rr][c4 + 3] = v.w;
            } else {
#pragma unroll
                for (int e = 0; e < 4; e++)
                    Bsm[rr][c4 + e] = (k < k1s && nn + e < N)
                                      ? W[(size_t)k * N + nn + e] : 0.f;
            }
        }
        __syncthreads();
#pragma unroll
        for (int kk = 0; kk < 16; kk++) {
            float bv = Bsm[kk][nl];
#pragma unroll
            for (int i = 0; i < 16; i++)
                acc[i] += Asm[mg * 16 + i][kk] * bv;
        }
        __syncthreads();
    }

    int nn = n0 + nl;
    if (nn < N) {
        float* outp = Ppart + (size_t)ks * 64 * N;
#pragma unroll
        for (int i = 0; i < 16; i++)
            outp[(size_t)(mg * 16 + i) * N + nn] = acc[i];
    }
}

__global__ void reduce_bias(const float* __restrict__ Ppart, const float* __restrict__ bias,
                            float* __restrict__ Y, int N, int KS)
{
    int idx = blockIdx.x * 256 + threadIdx.x;
    if (idx >= 64 * N) return;
    int nn = idx % N;
    float s = bias[nn];
    for (int ks = 0; ks < KS; ks++) s += Ppart[(size_t)ks * 64 * N + idx];
    Y[idx] = s;
}

// ---------------- launch ----------------
extern "C" void kernel_launch(void* const* d_in, const int* in_sizes, int n_in,
                              void* d_out, int out_size)
{
    const float* x1  = (const float*)d_in[0];
    const float* x2  = (const float*)d_in[1];
    const float* wx1 = (const float*)d_in[2];
    const float* wh1 = (const float*)d_in[3];
    const float* bx1 = (const float*)d_in[4];
    const float* bh1 = (const float*)d_in[5];
    const float* wx2 = (const float*)d_in[6];
    const float* wh2 = (const float*)d_in[7];
    const float* bx2 = (const float*)d_in[8];
    const float* bh2 = (const float*)d_in[9];
    const float* fw2 = (const float*)d_in[10];
    const float* fb2 = (const float*)d_in[11];
    const float* fw3 = (const float*)d_in[12];
    const float* fb3 = (const float*)d_in[13];
    const float* fw4 = (const float*)d_in[14];
    const float* fb4 = (const float*)d_in[15];
    const float* fw5 = (const float*)d_in[16];
    const float* fb5 = (const float*)d_in[17];

    float *feat, *y1, *y2, *y3, *part;
    cudaGetSymbolAddress((void**)&feat, g_feat);
    cudaGetSymbolAddress((void**)&y1,   g_y1);
    cudaGetSymbolAddress((void**)&y2,   g_y2);
    cudaGetSymbolAddress((void**)&y3,   g_y3);
    cudaGetSymbolAddress((void**)&part, g_part);

    cudaFuncSetAttribute(lstm_mma, cudaFuncAttributeMaxDynamicSharedMemorySize, SMEM_BYTES);

    lstm_mma<<<148, 512, SMEM_BYTES>>>(x1, x2, wx1, wh1, bx1, bh1,
                                       wx2, wh2, bx2, bh2, feat);

    // FC1: 7040 -> 3400
    gemm_part<<<dim3(54, 16), 256>>>(feat, fw2, part, 3400, 7040, 16);
    reduce_bias<<<(64 * 3400 + 255) / 256, 256>>>(part, fb2, y1, 3400, 16);
    // FC2: 3400 -> 1000
    gemm_part<<<dim3(16, 8), 256>>>(y1, fw3, part, 1000, 3400, 8);
    reduce_bias<<<(64 * 1000 + 255) / 256, 256>>>(part, fb3, y2, 1000, 8);
    // FC3: 1000 -> 500
    gemm_part<<<dim3(8, 4), 256>>>(y2, fw4, part, 500, 1000, 4);
    reduce_bias<<<(64 * 500 + 255) / 256, 256>>>(part, fb4, y3, 500, 4);
    // FC4: 500 -> 50 -> d_out
    gemm_part<<<dim3(1, 2), 256>>>(y3, fw5, part, 50, 500, 2);
    reduce_bias<<<(64 * 50 + 255) / 256, 256>>>(part, fb5, (float*)d_out, 50, 2);
}

// round 9
// speedup vs baseline: 5.9150x; 1.0415x over previous
#include <cuda_runtime.h>
#include <cuda_fp16.h>
#include <cstdint>

#define RS   88                 // halves per smem row (176 B)
#define MB   16                 // rows per block
#define ASZH (MB * RS)          // halves per A buffer
#define SMEM_BYTES ((2 * ASZH + 256 * RS) * 2)   // 50688

// ---------------- scratch ----------------
__device__ float g_feat[2 * 32 * 2 * 64 * 55];   // [sub][b][7040]
__device__ float g_y1[64 * 3400];
__device__ float g_y2[64 * 1000];
__device__ float g_y3[64 * 512];
__device__ float g_part[16 * 64 * 3400];

__device__ __forceinline__ float tanh_f(float x) {
    float r; asm("tanh.approx.f32 %0, %1;" : "=f"(r) : "f"(x)); return r;
}
// pre-activation already scaled by 0.5 (folded into weights)
__device__ __forceinline__ float sigm_pre(float xhalf) {
    return fmaf(0.5f, tanh_f(xhalf), 0.5f);
}

__device__ __forceinline__ uint32_t smem_u32(const void* p) {
    uint32_t a;
    asm("{ .reg .u64 t; cvta.to.shared.u64 t, %1; cvt.u32.u64 %0, t; }" : "=r"(a) : "l"(p));
    return a;
}

#define MMA16816(d, a0, a1, a2, a3, b0, b1) \
    asm volatile("mma.sync.aligned.m16n8k16.row.col.f32.f16.f16.f32 " \
        "{%0,%1,%2,%3}, {%4,%5,%6,%7}, {%8,%9}, {%0,%1,%2,%3};" \
        : "+f"((d)[0]), "+f"((d)[1]), "+f"((d)[2]), "+f"((d)[3]) \
        : "r"(a0), "r"(a1), "r"(a2), "r"(a3), "r"(b0), "r"(b1))

// ---------------- tensor-core LSTM (HMMA, 3 blocks/SM) ----------------
// grid = 440: blk/220 = cell, rb = (blk%220)*16 (exact, no padding).
// Warp w owns B cols [32w,32w+32): col n -> gate (n>>3)&3, channel 8w + (n&7).
// Lane owns rows {lane>>2, +8}, channels {8w+(lane&3)*2, +1}; full gate quad in-lane.
__global__ __launch_bounds__(256, 3)
void lstm_mma(const float* __restrict__ x1, const float* __restrict__ x2,
              const float* __restrict__ wx1, const float* __restrict__ wh1,
              const float* __restrict__ bx1, const float* __restrict__ bh1,
              const float* __restrict__ wx2, const float* __restrict__ wh2,
              const float* __restrict__ bx2, const float* __restrict__ bh2,
              float* __restrict__ feat)
{
    extern __shared__ __align__(16) __half smem[];
    __half* A0 = smem;
    __half* A1 = smem + ASZH;
    __half* Bw = smem + 2 * ASZH;

    int tid = threadIdx.x, wid = tid >> 5, lane = tid & 31;
    int blk = blockIdx.x;
    int cell = blk / 220;
    int rb   = (blk % 220) * MB;             // row base within cell-space (always full)

    const float* wh = cell ? wh2 : wh1;
    const float* wx = cell ? wx2 : wx1;
    const float* bx = cell ? bx2 : bx1;
    const float* bh = cell ? bh2 : bh1;

    // ---- build B (fp16, 0.5-prescaled for sigmoid gates i,f,o) ----
    {
        int n  = tid;
        int w  = n >> 5, g = (n >> 3) & 3, cl = n & 7;
        int gc = g * 64 + 8 * w + cl;        // source gate column
        float s = (g == 3) ? 1.0f : 0.5f;
        __half* bp = Bw + n * RS;
#pragma unroll 8
        for (int k = 0; k < 64; k++) bp[k] = __float2half(wh[k * 256 + gc] * s);
        bp[64] = __float2half(wx[gc] * s);
        bp[65] = __float2half(wx[256 + gc] * s);
        bp[66] = __float2half((bx[gc] + bh[gc]) * s);
#pragma unroll
        for (int k = 67; k < RS; k++) bp[k] = __float2half(0.f);
    }
    // ---- zero A buffers ----
    for (int i = tid; i < (2 * ASZH * 2) / 16; i += 256)
        ((uint4*)smem)[i] = make_uint4(0, 0, 0, 0);
    __syncthreads();

    // per-row x pointer (threads 0..15 own row tid)
    const float* xrp = nullptr;
    if (tid < MB) {
        int ric = rb + tid;
        int sub = ric / 1760, rem = ric % 1760, b = rem / 55, p = rem % 55;
        xrp = (sub ? x2 : x1) + (size_t)b * 256 * 110 + p;
        int t0 = cell ? 255 : 0;
        A0[tid * RS + 64] = __float2half(xrp[(size_t)t0 * 110]);
        A0[tid * RS + 65] = __float2half(xrp[(size_t)t0 * 110 + 55]);
        A0[tid * RS + 66] = __float2half(1.f);
        A1[tid * RS + 66] = __float2half(1.f);
    }
    __syncthreads();

    // B fragment base addresses (reloaded each step; keeps regs low for 3 blocks/SM)
    uint32_t baddr[4];
    {
        int li = lane & 15;
#pragma unroll
        for (int nt = 0; nt < 4; nt++)
            baddr[nt] = smem_u32(Bw + (wid * 32 + nt * 8 + (li & 7)) * RS
                                    + ((li >> 3) & 1) * 8);
    }

    uint32_t laneoff = (uint32_t)(((lane & 7) + 8 * ((lane >> 3) & 1)) * RS * 2
                                  + (lane >> 4) * 16);

    float cst[4] = {0.f, 0.f, 0.f, 0.f};     // rows {r0,r0+8} x chans {ch,ch+1}

    int r0 = lane >> 2;
    int ch = wid * 8 + (lane & 3) * 2;

    float xn0 = 0.f, xn1 = 0.f;

    for (int t = 0; t < 256; t++) {
        __half* Ac = (t & 1) ? A1 : A0;
        __half* An = (t & 1) ? A0 : A1;
        uint32_t abase = smem_u32(Ac) + laneoff;

        if (tid < MB && t < 255) {
            int tx = cell ? 254 - t : t + 1;
            xn0 = xrp[(size_t)tx * 110];
            xn1 = xrp[(size_t)tx * 110 + 55];
        }

        float acc[4][4];
#pragma unroll
        for (int nt = 0; nt < 4; nt++)
#pragma unroll
            for (int j = 0; j < 4; j++) acc[nt][j] = 0.f;

#pragma unroll
        for (int kt = 0; kt < 5; kt++) {
            uint32_t a0, a1, a2, a3;
            asm volatile("ldmatrix.sync.aligned.m8n8.x4.shared.b16 {%0,%1,%2,%3}, [%4];"
                         : "=r"(a0), "=r"(a1), "=r"(a2), "=r"(a3)
                         : "r"(abase + (uint32_t)(kt * 32)));
#pragma unroll
            for (int nt = 0; nt < 4; nt++) {
                uint32_t b0, b1;
                asm volatile("ldmatrix.sync.aligned.m8n8.x2.shared.b16 {%0,%1}, [%2];"
                             : "=r"(b0), "=r"(b1)
                             : "r"(baddr[nt] + (uint32_t)(kt * 32)));
                MMA16816(acc[nt], a0, a1, a2, a3, b0, b1);
            }
        }

        // epilogue: nt = gate (0:i 1:f 2:o 3:g); j: row-pair (j>>1), chan (j&1)
        float h01[2], h23[2];
#pragma unroll
        for (int j = 0; j < 4; j++) {
            float iv = sigm_pre(acc[0][j]);
            float fv = sigm_pre(acc[1][j]);
            float ov = sigm_pre(acc[2][j]);
            float gv = tanh_f(acc[3][j]);
            float cn = fmaf(fv, cst[j], iv * gv);
            cst[j] = cn;
            float h = ov * tanh_f(cn);
            if (j < 2) h01[j] = h; else h23[j - 2] = h;
        }
        *(__half2*)(An + r0 * RS + ch)       = __floats2half2_rn(h01[0], h01[1]);
        *(__half2*)(An + (r0 + 8) * RS + ch) = __floats2half2_rn(h23[0], h23[1]);

        if (t == 255) {
#pragma unroll
            for (int j = 0; j < 4; j++) {
                float h = (j < 2) ? h01[j] : h23[j - 2];
                int row = r0 + ((j >> 1) ? 8 : 0);
                int chh = ch + (j & 1);
                int ric = rb + row;
                int sub = ric / 1760, rem = ric % 1760, bb = rem / 55, pp = rem % 55;
                feat[(size_t)(sub * 32 + bb) * 7040 + cell * 3520 + chh * 55 + pp] = h;
            }
        }

        if (tid < MB && t < 255)
            *(__half2*)(An + tid * RS + 64) = __floats2half2_rn(xn0, xn1);

        __syncthreads();
    }
}

// ---------------- FC: K-split GEMM partials + reduce ----------------
__global__ __launch_bounds__(256)
void gemm_part(const float* __restrict__ X, const float* __restrict__ W,
               float* __restrict__ Ppart, int N, int K, int KS)
{
    int n0 = blockIdx.x * 64;
    int ks = blockIdx.y;
    int k0s = (int)(((long)K * ks) / KS);
    int k1s = (int)(((long)K * (ks + 1)) / KS);

    __shared__ float Asm[64][17];
    __shared__ float Bsm[16][65];

    int tid = threadIdx.x;
    int nl  = tid & 63;
    int mg  = tid >> 6;

    bool vec_ok = ((N & 3) == 0);   // float4 path only when W rows stay 16B-aligned

    float acc[16];
#pragma unroll
    for (int i = 0; i < 16; i++) acc[i] = 0.f;

    for (int k0 = k0s; k0 < k1s; k0 += 16) {
#pragma unroll
        for (int i = 0; i < 4; i++) {
            int rr = (tid >> 4) + i * 16;
            int cc = tid & 15;
            int k = k0 + cc;
            Asm[rr][cc] = (k < k1s) ? X[(size_t)rr * K + k] : 0.f;
        }
        {
            int rr = tid >> 4;            // 0..15
            int c4 = (tid & 15) * 4;      // 0..60
            int k  = k0 + rr;
            int nn = n0 + c4;
            if (vec_ok && k < k1s && nn + 3 < N) {
                float4 v = *(const float4*)&W[(size_t)k * N + nn];
                Bsm[rr][c4]     = v.x;
                Bsm[rr][c4 + 1] = v.y;
                Bsm[rr][c4 + 2] = v.z;
                Bsm[rr][c4 + 3] = v.w;
            } else {
#pragma unroll
                for (int e = 0; e < 4; e++)
                    Bsm[rr][c4 + e] = (k < k1s && nn + e < N)
                                      ? W[(size_t)k * N + nn + e] : 0.f;
            }
        }
        __syncthreads();
#pragma unroll
        for (int kk = 0; kk < 16; kk++) {
            float bv = Bsm[kk][nl];
#pragma unroll
            for (int i = 0; i < 16; i++)
                acc[i] += Asm[mg * 16 + i][kk] * bv;
        }
        __syncthreads();
    }

    int nn = n0 + nl;
    if (nn < N) {
        float* outp = Ppart + (size_t)ks * 64 * N;
#pragma unroll
        for (int i = 0; i < 16; i++)
            outp[(size_t)(mg * 16 + i) * N + nn] = acc[i];
    }
}

__global__ void reduce_bias(const float* __restrict__ Ppart, const float* __restrict__ bias,
                            float* __restrict__ Y, int N, int KS)
{
    int idx = blockIdx.x * 256 + threadIdx.x;
    if (idx >= 64 * N) return;
    int nn = idx % N;
    float s = bias[nn];
    for (int ks = 0; ks < KS; ks++) s += Ppart[(size_t)ks * 64 * N + idx];
    Y[idx] = s;
}

// ---------------- launch ----------------
extern "C" void kernel_launch(void* const* d_in, const int* in_sizes, int n_in,
                              void* d_out, int out_size)
{
    const float* x1  = (const float*)d_in[0];
    const float* x2  = (const float*)d_in[1];
    const float* wx1 = (const float*)d_in[2];
    const float* wh1 = (const float*)d_in[3];
    const float* bx1 = (const float*)d_in[4];
    const float* bh1 = (const float*)d_in[5];
    const float* wx2 = (const float*)d_in[6];
    const float* wh2 = (const float*)d_in[7];
    const float* bx2 = (const float*)d_in[8];
    const float* bh2 = (const float*)d_in[9];
    const float* fw2 = (const float*)d_in[10];
    const float* fb2 = (const float*)d_in[11];
    const float* fw3 = (const float*)d_in[12];
    const float* fb3 = (const float*)d_in[13];
    const float* fw4 = (const float*)d_in[14];
    const float* fb4 = (const float*)d_in[15];
    const float* fw5 = (const float*)d_in[16];
    const float* fb5 = (const float*)d_in[17];

    float *feat, *y1, *y2, *y3, *part;
    cudaGetSymbolAddress((void**)&feat, g_feat);
    cudaGetSymbolAddress((void**)&y1,   g_y1);
    cudaGetSymbolAddress((void**)&y2,   g_y2);
    cudaGetSymbolAddress((void**)&y3,   g_y3);
    cudaGetSymbolAddress((void**)&part, g_part);

    cudaFuncSetAttribute(lstm_mma, cudaFuncAttributeMaxDynamicSharedMemorySize, SMEM_BYTES);

    lstm_mma<<<440, 256, SMEM_BYTES>>>(x1, x2, wx1, wh1, bx1, bh1,
                                       wx2, wh2, bx2, bh2, feat);

    // FC1: 7040 -> 3400
    gemm_part<<<dim3(54, 16), 256>>>(feat, fw2, part, 3400, 7040, 16);
    reduce_bias<<<(64 * 3400 + 255) / 256, 256>>>(part, fb2, y1, 3400, 16);
    // FC2: 3400 -> 1000
    gemm_part<<<dim3(16, 8), 256>>>(y1, fw3, part, 1000, 3400, 8);
    reduce_bias<<<(64 * 1000 + 255) / 256, 256>>>(part, fb3, y2, 1000, 8);
    // FC3: 1000 -> 500
    gemm_part<<<dim3(8, 4), 256>>>(y2, fw4, part, 500, 1000, 4);
    reduce_bias<<<(64 * 500 + 255) / 256, 256>>>(part, fb4, y3, 500, 4);
    // FC4: 500 -> 50 -> d_out
    gemm_part<<<dim3(1, 2), 256>>>(y3, fw5, part, 50, 500, 2);
    reduce_bias<<<(64 * 50 + 255) / 256, 256>>>(part, fb5, (float*)d_out, 50, 2);
}